// round 3
// baseline (speedup 1.0000x reference)
#include <cuda_runtime.h>
#include <stdint.h>

// ---------------- configuration ----------------
#define H1_BITS   13
#define H1_BINS   (1 << H1_BITS)          // 8192 bins, key >> 18
#define H2_BITS   18
#define H2_BINS   (1 << H2_BITS)          // 262144 bins, key & 0x3FFFF
#define CHUNKS    256
#define CHUNK_SZ  (H2_BINS / CHUNKS)      // 1024

// ---------------- device scratch (no allocation allowed) ----------------
__device__ unsigned int g_hist1[H1_BINS];
__device__ unsigned int g_hist2[2][H2_BINS];
__device__ unsigned int g_chunk[2][CHUNKS];
__device__ unsigned int g_selBin[2];     // top-13-bit bin of each target rank
__device__ unsigned int g_selRank[2];    // residual descending rank within bin
__device__ float        g_t2;            // threshold squared

__device__ __forceinline__ unsigned int abskey(float v) {
    return __float_as_uint(v) & 0x7fffffffu;
}

// ---------------- pass 1: coarse 13-bit histogram (smem privatized) ----------------
__global__ void hist1_kernel(const float* __restrict__ w, int n4, int n) {
    __shared__ unsigned int sh[H1_BINS];  // 32 KB
    for (int i = threadIdx.x; i < H1_BINS; i += blockDim.x) sh[i] = 0u;
    __syncthreads();

    const float4* w4 = (const float4*)w;
    int stride = gridDim.x * blockDim.x;
    for (int i = blockIdx.x * blockDim.x + threadIdx.x; i < n4; i += stride) {
        float4 v = __ldg(&w4[i]);
        atomicAdd(&sh[abskey(v.x) >> H2_BITS], 1u);
        atomicAdd(&sh[abskey(v.y) >> H2_BITS], 1u);
        atomicAdd(&sh[abskey(v.z) >> H2_BITS], 1u);
        atomicAdd(&sh[abskey(v.w) >> H2_BITS], 1u);
    }
    if (blockIdx.x == 0) {  // tail (n not multiple of 4)
        for (int i = n4 * 4 + threadIdx.x; i < n; i += blockDim.x)
            atomicAdd(&sh[abskey(__ldg(&w[i])) >> H2_BITS], 1u);
    }
    __syncthreads();
    for (int i = threadIdx.x; i < H1_BINS; i += blockDim.x) {
        unsigned int c = sh[i];
        if (c) atomicAdd(&g_hist1[i], c);
    }
}

// ---------------- scan 1: locate coarse bin for ranks kH and kH+1 ----------------
__global__ void scan1_kernel(unsigned int kH) {
    __shared__ unsigned int sh[H1_BINS];
    __shared__ unsigned int csum[1024];
    int tid = threadIdx.x;
    for (int i = tid; i < H1_BINS; i += blockDim.x) sh[i] = g_hist1[i];
    __syncthreads();
    unsigned int s = 0;
    #pragma unroll
    for (int j = 0; j < H1_BINS / 1024; j++) s += sh[tid * (H1_BINS / 1024) + j];
    csum[tid] = s;
    __syncthreads();

    if (tid < 2) {                         // thread t handles descending rank kH+t
        unsigned int k = kH + tid;
        unsigned int cum = 0;
        int c = 1023;
        for (; c >= 0; c--) {              // descending over chunk sums
            unsigned int nc = cum + csum[c];
            if (nc > k) break;
            cum = nc;
        }
        const int W = H1_BINS / 1024;      // 8 bins per chunk
        int b = c * W + (W - 1);
        for (;; b--) {
            unsigned int nb = cum + sh[b];
            if (nb > k) break;
            cum = nb;
        }
        g_selBin[tid]  = (unsigned int)b;
        g_selRank[tid] = k - cum;
    }
}

// ---------------- pass 2: refine low 18 bits for the selected bin(s) ----------------
__global__ void hist2_kernel(const float* __restrict__ w, int n4, int n) {
    unsigned int bH = g_selBin[0];
    unsigned int bT = g_selBin[1];
    const float4* w4 = (const float4*)w;
    int stride = gridDim.x * blockDim.x;
    for (int i = blockIdx.x * blockDim.x + threadIdx.x; i < n4; i += stride) {
        float4 v = __ldg(&w4[i]);
        float e[4] = {v.x, v.y, v.z, v.w};
        #pragma unroll
        for (int j = 0; j < 4; j++) {
            unsigned int key = abskey(e[j]);
            unsigned int hb  = key >> H2_BITS;
            if (hb == bH)      atomicAdd(&g_hist2[0][key & (H2_BINS - 1)], 1u);
            else if (hb == bT) atomicAdd(&g_hist2[1][key & (H2_BINS - 1)], 1u);
        }
    }
    if (blockIdx.x == 0) {
        for (int i = n4 * 4 + threadIdx.x; i < n; i += blockDim.x) {
            unsigned int key = abskey(__ldg(&w[i]));
            unsigned int hb  = key >> H2_BITS;
            if (hb == bH)      atomicAdd(&g_hist2[0][key & (H2_BINS - 1)], 1u);
            else if (hb == bT) atomicAdd(&g_hist2[1][key & (H2_BINS - 1)], 1u);
        }
    }
}

// ---------------- scan A: per-chunk sums of the fine histograms ----------------
__global__ void scanA_kernel() {
    __shared__ unsigned int red[256];
    int t = blockIdx.y;
    int c = blockIdx.x;
    const uint4* p = (const uint4*)(&g_hist2[t][c * CHUNK_SZ]);
    uint4 v = p[threadIdx.x];              // 256 threads * 4 bins = 1024 bins
    red[threadIdx.x] = v.x + v.y + v.z + v.w;
    __syncthreads();
    for (int o = 128; o > 0; o >>= 1) {
        if (threadIdx.x < o) red[threadIdx.x] += red[threadIdx.x + o];
        __syncthreads();
    }
    if (threadIdx.x == 0) g_chunk[t][c] = red[0];
}

// ---------------- scan B: recover exact keys, compute threshold ----------------
__global__ void scanB_kernel() {
    __shared__ unsigned int schunk[CHUNKS];
    __shared__ unsigned int sbins[CHUNK_SZ];
    __shared__ int s_c;
    __shared__ unsigned int s_cum;
    __shared__ float vals[2];

    unsigned int bH = g_selBin[0];
    unsigned int bT = g_selBin[1];

    for (int t = 0; t < 2; t++) {
        int sidx = (t == 1 && bT == bH) ? 0 : t;   // same coarse bin -> same fine hist
        unsigned int k = g_selRank[t];

        if (threadIdx.x < CHUNKS) schunk[threadIdx.x] = g_chunk[sidx][threadIdx.x];
        __syncthreads();

        if (threadIdx.x == 0) {
            unsigned int cum = 0;
            int c = CHUNKS - 1;
            for (; c >= 0; c--) {
                unsigned int nc = cum + schunk[c];
                if (nc > k) break;
                cum = nc;
            }
            s_c = c; s_cum = cum;
        }
        __syncthreads();

        int c = s_c;
        sbins[threadIdx.x] = g_hist2[sidx][c * CHUNK_SZ + threadIdx.x];
        __syncthreads();

        if (threadIdx.x == 0) {
            unsigned int cum = s_cum;
            int b = CHUNK_SZ - 1;
            for (;; b--) {
                unsigned int nb = cum + sbins[b];
                if (nb > k) break;
                cum = nb;
            }
            unsigned int bin = (t == 0) ? bH : bT;
            unsigned int key = (bin << H2_BITS) | (unsigned int)(c * CHUNK_SZ + b);
            vals[t] = __uint_as_float(key);
        }
        __syncthreads();
    }
    if (threadIdx.x == 0) {
        float th = 0.5f * (vals[0] + vals[1]);
        g_t2 = th * th;
    }
}

// ---------------- pass 3: elementwise mask * weight ----------------
__device__ __forceinline__ float pdp_mask(float v, float t2) {
    float x = (v * v - t2) / 0.01f;        // (w^2 - t^2) / TEMP
    return 1.0f / (1.0f + expf(-x));
}

__global__ void final_kernel(const float* __restrict__ w, float* __restrict__ out,
                             int n4, int n) {
    float t2 = g_t2;
    const float4* w4 = (const float4*)w;
    float4* o4 = (float4*)out;
    int stride = gridDim.x * blockDim.x;
    for (int i = blockIdx.x * blockDim.x + threadIdx.x; i < n4; i += stride) {
        float4 v = __ldg(&w4[i]);
        float4 r;
        r.x = pdp_mask(v.x, t2) * v.x;
        r.y = pdp_mask(v.y, t2) * v.y;
        r.z = pdp_mask(v.z, t2) * v.z;
        r.w = pdp_mask(v.w, t2) * v.w;
        o4[i] = r;
    }
    if (blockIdx.x == 0) {
        for (int i = n4 * 4 + threadIdx.x; i < n; i += blockDim.x) {
            float v = __ldg(&w[i]);
            out[i] = pdp_mask(v, t2) * v;
        }
    }
}

// ---------------- launch ----------------
extern "C" void kernel_launch(void* const* d_in, const int* in_sizes, int n_in,
                              void* d_out, int out_size) {
    const float* w = (const float*)d_in[0];
    float* out = (float*)d_out;
    int n  = in_sizes[0];
    int n4 = n >> 2;

    // ind = int((1 - 0.9) * n) - 1, clipped to [0, n-2]  (match reference arithmetic)
    long long ind = (long long)((1.0 - 0.9) * (double)n) - 1;
    if (ind < 0) ind = 0;
    if (ind > (long long)n - 2) ind = (long long)n - 2;
    unsigned int kH = (unsigned int)ind;

    void *p1 = nullptr, *p2 = nullptr;
    cudaGetSymbolAddress(&p1, g_hist1);
    cudaGetSymbolAddress(&p2, g_hist2);
    cudaMemsetAsync(p1, 0, sizeof(g_hist1));
    cudaMemsetAsync(p2, 0, sizeof(g_hist2));

    hist1_kernel<<<592, 512>>>(w, n4, n);
    scan1_kernel<<<1, 1024>>>(kH);
    hist2_kernel<<<592, 512>>>(w, n4, n);
    dim3 gA(CHUNKS, 2);
    scanA_kernel<<<gA, 256>>>();
    scanB_kernel<<<1, 1024>>>();
    final_kernel<<<2368, 256>>>(w, out, n4, n);
}